// round 6
// baseline (speedup 1.0000x reference)
#include <cuda_runtime.h>
#include <cstdint>
#include <cstddef>
#include <math.h>

// Problem constants (fixed by setup_inputs)
constexpr int cB = 2, cL = 2048, cD = 256, cP = 16, cK = 4, cI = 3;
constexpr int cF = 32;
constexpr int cKD = 1024;
constexpr int cH = 512;
constexpr int cCH = 64;
constexpr int cNC = cL / cCH;
constexpr int cM = cB * cL;
#define PI_F 3.14159265358979323846f

// ---------------- scratch ---------------------------------------------------
__device__ float g_V[cM * cD];
__device__ float g_Mfeat[cB * cK * cL * cF];
__device__ float g_Qfeat[cB * cK * cL * cF];
__device__ float g_state[cB * cK * cNC * cF * cD];
__device__ float g_comb[cM * cKD];
__device__ float g_combln[cM * cKD];
__device__ float g_h[cM * cH];
__device__ float g_ref[cM * cD];
__device__ float g_acc[cM * cD];
__device__ float g_q0[cM * cD];
__device__ float g_q1[cM * cD];
__device__ float g_accln[cM * cD];

// ---------------- tf32 helpers ---------------------------------------------
__device__ __forceinline__ uint32_t f2tf(float x) {
    uint32_t r;
    asm("cvt.rna.tf32.f32 %0, %1;" : "=r"(r) : "f"(x));
    return r;
}
__device__ __forceinline__ void mma_tf32(float* c, const uint32_t* a, const uint32_t* b) {
    asm volatile(
        "mma.sync.aligned.m16n8k8.row.col.f32.tf32.tf32.f32 "
        "{%0,%1,%2,%3}, {%4,%5,%6,%7}, {%8,%9}, {%0,%1,%2,%3};\n"
        : "+f"(c[0]), "+f"(c[1]), "+f"(c[2]), "+f"(c[3])
        : "r"(a[0]), "r"(a[1]), "r"(a[2]), "r"(a[3]), "r"(b[0]), "r"(b[1]));
}
__device__ __forceinline__ void cp_async16(void* smem_dst, const void* gsrc) {
    uint32_t s = (uint32_t)__cvta_generic_to_shared(smem_dst);
    asm volatile("cp.async.cg.shared.global [%0], [%1], 16;\n" :: "r"(s), "l"(gsrc));
}

// ---------------- tf32 tensor-core GEMM, cp.async double-buffered ----------
// C = epi(A @ W^T + bias). A: M x KDIM (SPLITA: [A|A2] each M x cD). W: N x KDIM.
// BM=128, BN=128, BK=16, 256 thr, warp grid 2(m) x 4(n), warp tile 64x32.
// Static smem: 2 stages x (128*20 + 128*20) floats = 40960 B (< 48 KB, no opt-in)
constexpr int GSA = 20;                  // padded row stride (floats)
constexpr int GS_A = 128 * GSA;          // floats per A stage
constexpr int GS_W = 128 * GSA;          // floats per W stage
constexpr int GS_STAGE = GS_A + GS_W;    // 5120 floats

template<int KDIM, int EPI, bool SPLITA>
__global__ __launch_bounds__(256) void mma_gemm_k(
    const float* __restrict__ A, const float* __restrict__ A2,
    const float* __restrict__ W, const float* __restrict__ bias,
    float* __restrict__ C, float* __restrict__ aux,
    const float* __restrict__ addsrc, int N, int flag)
{
    __shared__ float dsm[2 * GS_STAGE];
    const int tid = threadIdx.x;
    const int warp = tid >> 5, lane = tid & 31;
    const int wm = warp >> 2, wn = warp & 3;      // 2 x 4 warp grid
    const int gid = lane >> 2, tig = lane & 3;
    const int m0 = blockIdx.y * 128;
    const int n0 = blockIdx.x * 128;
    const int lda = SPLITA ? cD : KDIM;
    constexpr int NK = KDIM / 16;

    auto issue_stage = [&](int s, int k0) {
        float* As = dsm + s * GS_STAGE;
        float* Ws = As + GS_A;
        const float* Ap = A;
        int kb = k0;
        if (SPLITA && k0 >= cD) { Ap = A2; kb = k0 - cD; }
        // A tile: 128 x 16 floats = 512 float4, 2 per thread
#pragma unroll
        for (int r = 0; r < 2; r++) {
            int idx4 = tid + r * 256;
            int mm = idx4 >> 2, q = idx4 & 3;
            cp_async16(&As[mm * GSA + q * 4],
                       &Ap[(size_t)(m0 + mm) * lda + kb + q * 4]);
        }
        // W tile: 128 x 16 floats = 512 float4, 2 per thread
#pragma unroll
        for (int r = 0; r < 2; r++) {
            int idx4 = tid + r * 256;
            int nn = idx4 >> 2, q = idx4 & 3;
            cp_async16(&Ws[nn * GSA + q * 4],
                       &W[(size_t)(n0 + nn) * KDIM + k0 + q * 4]);
        }
    };

    float acc[4][4][4];
#pragma unroll
    for (int i = 0; i < 4; i++)
#pragma unroll
        for (int j = 0; j < 4; j++)
#pragma unroll
            for (int r = 0; r < 4; r++) acc[i][j][r] = 0.f;

    issue_stage(0, 0);
    asm volatile("cp.async.commit_group;\n");

    for (int t = 0; t < NK; t++) {
        if (t + 1 < NK) {
            issue_stage((t + 1) & 1, (t + 1) * 16);
            asm volatile("cp.async.commit_group;\n");
            asm volatile("cp.async.wait_group 1;\n");
        } else {
            asm volatile("cp.async.wait_group 0;\n");
        }
        __syncthreads();
        const float* As = dsm + (t & 1) * GS_STAGE;
        const float* Ws = As + GS_A;
#pragma unroll
        for (int ks = 0; ks < 2; ks++) {
            int kk = ks * 8;
            uint32_t a[4][4], b[4][2];
#pragma unroll
            for (int i = 0; i < 4; i++) {
                int mb = wm * 64 + i * 16;
                a[i][0] = __float_as_uint(As[(mb + gid) * GSA + kk + tig]);
                a[i][1] = __float_as_uint(As[(mb + gid + 8) * GSA + kk + tig]);
                a[i][2] = __float_as_uint(As[(mb + gid) * GSA + kk + tig + 4]);
                a[i][3] = __float_as_uint(As[(mb + gid + 8) * GSA + kk + tig + 4]);
            }
#pragma unroll
            for (int j = 0; j < 4; j++) {
                int nb = wn * 32 + j * 8;
                b[j][0] = __float_as_uint(Ws[(nb + gid) * GSA + kk + tig]);
                b[j][1] = __float_as_uint(Ws[(nb + gid) * GSA + kk + tig + 4]);
            }
#pragma unroll
            for (int i = 0; i < 4; i++)
#pragma unroll
                for (int j = 0; j < 4; j++) mma_tf32(acc[i][j], a[i], b[j]);
        }
        __syncthreads();
    }

#pragma unroll
    for (int i = 0; i < 4; i++)
#pragma unroll
        for (int j = 0; j < 4; j++)
#pragma unroll
            for (int r = 0; r < 4; r++) {
                int m = m0 + wm * 64 + i * 16 + gid + ((r >= 2) ? 8 : 0);
                int n = n0 + wn * 32 + j * 8 + tig * 2 + (r & 1);
                float v = acc[i][j][r] + bias[n];
                if constexpr (EPI == 0) {
                    C[(size_t)m * N + n] = v;
                } else if constexpr (EPI == 2) {
                    v = 0.5f * v * (1.f + erff(v * 0.7071067811865476f));
                    C[(size_t)m * N + n] = v;
                } else if constexpr (EPI == 3) {
                    size_t o = (size_t)m * N + n;
                    C[o] = v;
                    aux[o] = flag ? v : (aux[o] + v);
                } else if constexpr (EPI == 4) {
                    size_t o = (size_t)m * N + n;
                    C[o] = addsrc[o] + tanhf(v);
                } else if constexpr (EPI == 5) {
                    size_t o = (size_t)m * N + n;
                    C[o] = addsrc[o] + v;
                }
            }
}

// ---------------- fp32 phase GEMM, BM=32 for full-chip occupancy -----------
__global__ __launch_bounds__(256) void phase_gemm_k(
    const float* __restrict__ A, const float* __restrict__ W,
    const float* __restrict__ bias, float* __restrict__ C)
{
    __shared__ float As[32][17];
    __shared__ float Ws[64][17];
    const int tid = threadIdx.x;
    const int tx = tid & 15, ty = tid >> 4;
    const int m0 = blockIdx.x * 32;
    constexpr int KDIM = 256;

    float acc[2][4];
#pragma unroll
    for (int i = 0; i < 2; i++)
#pragma unroll
        for (int j = 0; j < 4; j++) acc[i][j] = 0.f;

    for (int k0 = 0; k0 < KDIM; k0 += 16) {
        if (tid < 128) {
            int mm = tid >> 2, q = tid & 3;
            float4 a4 = *reinterpret_cast<const float4*>(
                &A[(size_t)(m0 + mm) * KDIM + k0 + q * 4]);
            As[mm][q * 4 + 0] = a4.x; As[mm][q * 4 + 1] = a4.y;
            As[mm][q * 4 + 2] = a4.z; As[mm][q * 4 + 3] = a4.w;
        }
        {
            int nn = tid >> 2, q = tid & 3;
            float4 w4 = *reinterpret_cast<const float4*>(
                &W[(size_t)nn * KDIM + k0 + q * 4]);
            Ws[nn][q * 4 + 0] = w4.x; Ws[nn][q * 4 + 1] = w4.y;
            Ws[nn][q * 4 + 2] = w4.z; Ws[nn][q * 4 + 3] = w4.w;
        }
        __syncthreads();
#pragma unroll
        for (int kk = 0; kk < 16; kk++) {
            float ra[2], rb[4];
#pragma unroll
            for (int i = 0; i < 2; i++) ra[i] = As[ty * 2 + i][kk];
#pragma unroll
            for (int j = 0; j < 4; j++) rb[j] = Ws[tx * 4 + j][kk];
#pragma unroll
            for (int i = 0; i < 2; i++)
#pragma unroll
                for (int j = 0; j < 4; j++) acc[i][j] = fmaf(ra[i], rb[j], acc[i][j]);
        }
        __syncthreads();
    }

#pragma unroll
    for (int i = 0; i < 2; i++) {
        int m = m0 + ty * 2 + i;
#pragma unroll
        for (int j = 0; j < 4; j++) {
            int n = tx * 4 + j;
            float v = acc[i][j] + bias[n];
            float t = tanhf(v) * PI_F;
            float sn, cs;
            sincosf(t, &sn, &cs);
            int bb = m / cL, l = m % cL;
            int kbank = n >> 4, p = n & 15;
            size_t base = ((size_t)(bb * cK + kbank) * cL + l) * cF;
            C[base + p] = cs;
            C[base + cP + p] = sn;
        }
    }
}

// ------------- per-chunk feature^T @ V partial sums ------------------------
__global__ __launch_bounds__(256) void chunk_partial_k(
    const float* __restrict__ mfeat, const float* __restrict__ V,
    float* __restrict__ state)
{
    const int ci = blockIdx.x, bk = blockIdx.y;
    const int bb = bk >> 2, kk = bk & 3;
    const int d = threadIdx.x;
    __shared__ float sMf[cCH * cF];
    const size_t featBase = ((size_t)(bb * cK + kk) * cL + (size_t)ci * cCH) * cF;
    for (int r = 0; r < 8; r++) sMf[d + r * 256] = mfeat[featBase + d + r * 256];
    __syncthreads();
    float acc[cF];
#pragma unroll
    for (int f = 0; f < cF; f++) acc[f] = 0.f;
    const float* vp = V + ((size_t)(bb * cL) + (size_t)ci * cCH) * cD;
    for (int l = 0; l < cCH; l++) {
        float v = vp[(size_t)l * cD + d];
#pragma unroll
        for (int f = 0; f < cF; f++) acc[f] = fmaf(sMf[l * cF + f], v, acc[f]);
    }
    float* st = state + (((size_t)(bb * cK + kk) * cNC + ci) * cF) * cD + d;
#pragma unroll
    for (int f = 0; f < cF; f++) st[(size_t)f * cD] = acc[f];
}

// ------------- exclusive prefix scan of chunk states over ci ---------------
__global__ __launch_bounds__(256) void scan_k(float* __restrict__ state)
{
    int u = blockIdx.x * 256 + threadIdx.x;
    if (u >= cB * cK * cF * cD) return;
    int fd = u & (cF * cD - 1);
    int bk = u >> 13;
    float* base = state + (size_t)bk * cNC * cF * cD + fd;
    float run = 0.f;
    for (int ci = 0; ci < cNC; ci++) {
        float t = base[(size_t)ci * cF * cD];
        base[(size_t)ci * cF * cD] = run;
        run += t;
    }
}

// ------------- retrieval via tf32 mma: R = Qf@S + tril(Qf@Mf^T)@V ----------
__global__ __launch_bounds__(256) void retrieve_mma_k(
    const float* __restrict__ qfeat, const float* __restrict__ mfeat,
    const float* __restrict__ state, const float* __restrict__ V,
    float* __restrict__ comb)
{
    constexpr int SQ = 36;
    constexpr int SAs = 68;
    constexpr int SB = 72;
    __shared__ uint32_t sQ[64 * SQ];
    __shared__ uint32_t sA[64 * SAs];
    __shared__ uint32_t sB[64 * SB];

    const int ci = blockIdx.x;
    const int bk = blockIdx.y;
    const int bb = bk >> 2, kb = bk & 3;
    const int tid = threadIdx.x;
    const int warp = tid >> 5, lane = tid & 31;
    const int wm2 = warp >> 2, wn4 = warp & 3;
    const int gid = lane >> 2, tig = lane & 3;

    const size_t featBase = ((size_t)(bb * cK + kb) * cL + (size_t)ci * cCH) * cF;
#pragma unroll
    for (int r = 0; r < 2; r++) {
        int idx4 = tid + r * 256;
        int row = idx4 >> 3, q = idx4 & 7;
        float4 a4 = *reinterpret_cast<const float4*>(&qfeat[featBase + (size_t)row * cF + q * 4]);
        uint32_t* s = &sQ[row * SQ + q * 4];
        s[0] = f2tf(a4.x); s[1] = f2tf(a4.y); s[2] = f2tf(a4.z); s[3] = f2tf(a4.w);
        float4 m4 = *reinterpret_cast<const float4*>(&mfeat[featBase + (size_t)row * cF + q * 4]);
        uint32_t* t = &sB[row * SQ + q * 4];
        t[0] = f2tf(m4.x); t[1] = f2tf(m4.y); t[2] = f2tf(m4.z); t[3] = f2tf(m4.w);
    }
    __syncthreads();

    // A = tril(Qf @ Mf^T)
    {
        float accA[2][2][4];
#pragma unroll
        for (int i = 0; i < 2; i++)
#pragma unroll
            for (int j = 0; j < 2; j++)
#pragma unroll
                for (int r = 0; r < 4; r++) accA[i][j][r] = 0.f;
#pragma unroll
        for (int ks = 0; ks < 4; ks++) {
            int kk = ks * 8;
            uint32_t a[2][4], b[2][2];
#pragma unroll
            for (int i = 0; i < 2; i++) {
                int mb = wm2 * 32 + i * 16;
                a[i][0] = sQ[(mb + gid) * SQ + kk + tig];
                a[i][1] = sQ[(mb + gid + 8) * SQ + kk + tig];
                a[i][2] = sQ[(mb + gid) * SQ + kk + tig + 4];
                a[i][3] = sQ[(mb + gid + 8) * SQ + kk + tig + 4];
            }
#pragma unroll
            for (int j = 0; j < 2; j++) {
                int nb = wn4 * 16 + j * 8;
                b[j][0] = sB[(nb + gid) * SQ + kk + tig];
                b[j][1] = sB[(nb + gid) * SQ + kk + tig + 4];
            }
#pragma unroll
            for (int i = 0; i < 2; i++)
#pragma unroll
                for (int j = 0; j < 2; j++) mma_tf32(accA[i][j], a[i], b[j]);
        }
        __syncthreads();
#pragma unroll
        for (int i = 0; i < 2; i++)
#pragma unroll
            for (int j = 0; j < 2; j++)
#pragma unroll
                for (int r = 0; r < 4; r++) {
                    int m = wm2 * 32 + i * 16 + gid + ((r >= 2) ? 8 : 0);
                    int n = wn4 * 16 + j * 8 + tig * 2 + (r & 1);
                    float v = (n <= m) ? accA[i][j][r] : 0.f;
                    sA[m * SAs + n] = f2tf(v);
                }
    }
    __syncthreads();

    const size_t stBase = (((size_t)(bb * cK + kb) * cNC + ci) * cF) * cD;
    const size_t vBase = ((size_t)(bb * cL) + (size_t)ci * cCH) * cD;

    for (int dh = 0; dh < 4; dh++) {
        __syncthreads();
#pragma unroll
        for (int r = 0; r < 2; r++) {
            int idx4 = tid + r * 256;
            int f = idx4 >> 4, q = idx4 & 15;
            float4 s4 = *reinterpret_cast<const float4*>(&state[stBase + (size_t)f * cD + dh * 64 + q * 4]);
            uint32_t* s = &sB[f * SB + q * 4];
            s[0] = f2tf(s4.x); s[1] = f2tf(s4.y); s[2] = f2tf(s4.z); s[3] = f2tf(s4.w);
        }
        __syncthreads();

        float accO[2][2][4];
#pragma unroll
        for (int i = 0; i < 2; i++)
#pragma unroll
            for (int j = 0; j < 2; j++)
#pragma unroll
                for (int r = 0; r < 4; r++) accO[i][j][r] = 0.f;

#pragma unroll
        for (int ks = 0; ks < 4; ks++) {
            int kk = ks * 8;
            uint32_t a[2][4], b[2][2];
#pragma unroll
            for (int i = 0; i < 2; i++) {
                int mb = wm2 * 32 + i * 16;
                a[i][0] = sQ[(mb + gid) * SQ + kk + tig];
                a[i][1] = sQ[(mb + gid + 8) * SQ + kk + tig];
                a[i][2] = sQ[(mb + gid) * SQ + kk + tig + 4];
                a[i][3] = sQ[(mb + gid + 8) * SQ + kk + tig + 4];
            }
#pragma unroll
            for (int j = 0; j < 2; j++) {
                int nb = wn4 * 16 + j * 8;
                b[j][0] = sB[(kk + tig) * SB + nb + gid];
                b[j][1] = sB[(kk + tig + 4) * SB + nb + gid];
            }
#pragma unroll
            for (int i = 0; i < 2; i++)
#pragma unroll
                for (int j = 0; j < 2; j++) mma_tf32(accO[i][j], a[i], b[j]);
        }
        __syncthreads();
#pragma unroll
        for (int r = 0; r < 4; r++) {
            int idx4 = tid + r * 256;
            int row = idx4 >> 4, q = idx4 & 15;
            float4 v4 = *reinterpret_cast<const float4*>(&V[vBase + (size_t)row * cD + dh * 64 + q * 4]);
            uint32_t* s = &sB[row * SB + q * 4];
            s[0] = f2tf(v4.x); s[1] = f2tf(v4.y); s[2] = f2tf(v4.z); s[3] = f2tf(v4.w);
        }
        __syncthreads();

#pragma unroll
        for (int ks = 0; ks < 8; ks++) {
            int kk = ks * 8;
            uint32_t a[2][4], b[2][2];
#pragma unroll
            for (int i = 0; i < 2; i++) {
                int mb = wm2 * 32 + i * 16;
                a[i][0] = sA[(mb + gid) * SAs + kk + tig];
                a[i][1] = sA[(mb + gid + 8) * SAs + kk + tig];
                a[i][2] = sA[(mb + gid) * SAs + kk + tig + 4];
                a[i][3] = sA[(mb + gid + 8) * SAs + kk + tig + 4];
            }
#pragma unroll
            for (int j = 0; j < 2; j++) {
                int nb = wn4 * 16 + j * 8;
                b[j][0] = sB[(kk + tig) * SB + nb + gid];
                b[j][1] = sB[(kk + tig + 4) * SB + nb + gid];
            }
#pragma unroll
            for (int i = 0; i < 2; i++)
#pragma unroll
                for (int j = 0; j < 2; j++) mma_tf32(accO[i][j], a[i], b[j]);
        }

#pragma unroll
        for (int i = 0; i < 2; i++)
#pragma unroll
            for (int j = 0; j < 2; j++)
#pragma unroll
                for (int r = 0; r < 4; r++) {
                    int ml = wm2 * 32 + i * 16 + gid + ((r >= 2) ? 8 : 0);
                    int nl = wn4 * 16 + j * 8 + tig * 2 + (r & 1);
                    int l = ci * cCH + ml;
                    float sc = rsqrtf(16.f * (float)(l + 1));
                    comb[((size_t)(bb * cL + l)) * cKD + (size_t)kb * cD + dh * 64 + nl] =
                        accO[i][j][r] * sc;
                }
    }
}

// ------------- row LayerNorm ------------------------------------------------
template<int NDIM>
__global__ __launch_bounds__(256) void ln_k(
    const float* __restrict__ in, const float* __restrict__ w,
    const float* __restrict__ bsh, float* __restrict__ out)
{
    const int row = blockIdx.x;
    const float* xp = in + (size_t)row * NDIM;
    constexpr int R = NDIM / 256;
    float vals[R];
    float s = 0.f, s2 = 0.f;
#pragma unroll
    for (int r = 0; r < R; r++) {
        float v = xp[threadIdx.x + r * 256];
        vals[r] = v; s += v; s2 += v * v;
    }
#pragma unroll
    for (int o = 16; o > 0; o >>= 1) {
        s += __shfl_xor_sync(0xffffffffu, s, o);
        s2 += __shfl_xor_sync(0xffffffffu, s2, o);
    }
    __shared__ float rs[8], rs2[8], sm[2];
    int wid = threadIdx.x >> 5, lane = threadIdx.x & 31;
    if (lane == 0) { rs[wid] = s; rs2[wid] = s2; }
    __syncthreads();
    if (threadIdx.x == 0) {
        float a = 0.f, c = 0.f;
        for (int i = 0; i < 8; i++) { a += rs[i]; c += rs2[i]; }
        float mean = a / NDIM;
        float var = c / NDIM - mean * mean;
        sm[0] = mean;
        sm[1] = rsqrtf(fmaxf(var, 0.f) + 1e-5f);
    }
    __syncthreads();
    float mean = sm[0], inv = sm[1];
    float* op = out + (size_t)row * NDIM;
#pragma unroll
    for (int r = 0; r < R; r++) {
        int i = threadIdx.x + r * 256;
        op[i] = (vals[r] - mean) * inv * w[i] + bsh[i];
    }
}

// ------------- host orchestration ------------------------------------------
extern "C" void kernel_launch(void* const* d_in, const int* in_sizes, int n_in,
                              void* d_out, int out_size)
{
    const float* x       = (const float*)d_in[0];
    const float* phase_w = (const float*)d_in[1];
    const float* phase_b = (const float*)d_in[2];
    const float* val_w   = (const float*)d_in[3];
    const float* val_b   = (const float*)d_in[4];
    const float* rlnw    = (const float*)d_in[5];
    const float* rlnb    = (const float*)d_in[6];
    const float* r1w     = (const float*)d_in[7];
    const float* r1b     = (const float*)d_in[8];
    const float* r2w     = (const float*)d_in[9];
    const float* r2b     = (const float*)d_in[10];
    const float* quw     = (const float*)d_in[11];
    const float* qub     = (const float*)d_in[12];
    const float* olnw    = (const float*)d_in[13];
    const float* olnb    = (const float*)d_in[14];
    const float* outw    = (const float*)d_in[15];
    const float* outb    = (const float*)d_in[16];
    float* out = (float*)d_out;

    float *V, *Mf, *Qf, *St, *Cb, *Cl, *Hh, *Rf, *Ac, *Q0, *Q1, *Al;
    cudaGetSymbolAddress((void**)&V,  g_V);
    cudaGetSymbolAddress((void**)&Mf, g_Mfeat);
    cudaGetSymbolAddress((void**)&Qf, g_Qfeat);
    cudaGetSymbolAddress((void**)&St, g_state);
    cudaGetSymbolAddress((void**)&Cb, g_comb);
    cudaGetSymbolAddress((void**)&Cl, g_combln);
    cudaGetSymbolAddress((void**)&Hh, g_h);
    cudaGetSymbolAddress((void**)&Rf, g_ref);
    cudaGetSymbolAddress((void**)&Ac, g_acc);
    cudaGetSymbolAddress((void**)&Q0, g_q0);
    cudaGetSymbolAddress((void**)&Q1, g_q1);
    cudaGetSymbolAddress((void**)&Al, g_accln);

    // values GEMM (tf32 mma): (4096x256) @ (256x256)^T
    mma_gemm_k<256, 0, false><<<dim3(cD / 128, cM / 128), 256>>>(
        x, nullptr, val_w, val_b, V, nullptr, nullptr, cD, 0);
    // memory-side phase features (fp32)
    phase_gemm_k<<<cM / 32, 256>>>(x, phase_w, phase_b, Mf);
    chunk_partial_k<<<dim3(cNC, cB * cK), 256>>>(Mf, V, St);
    scan_k<<<256, 256>>>(St);

    const float* qin = x;
    for (int i = 0; i < cI; i++) {
        float* qout = (i & 1) ? Q1 : Q0;
        phase_gemm_k<<<cM / 32, 256>>>(qin, phase_w, phase_b, Qf);
        retrieve_mma_k<<<dim3(cNC, cB * cK), 256>>>(Qf, Mf, St, V, Cb);
        ln_k<1024><<<cM, 256>>>(Cb, rlnw + (size_t)i * cKD, rlnb + (size_t)i * cKD, Cl);
        mma_gemm_k<1024, 2, false><<<dim3(cH / 128, cM / 128), 256>>>(
            Cl, nullptr, r1w + (size_t)i * cH * cKD, r1b + (size_t)i * cH,
            Hh, nullptr, nullptr, cH, 0);
        mma_gemm_k<512, 3, false><<<dim3(cD / 128, cM / 128), 256>>>(
            Hh, nullptr, r2w + (size_t)i * cD * cH, r2b + (size_t)i * cD,
            Rf, Ac, nullptr, cD, (i == 0) ? 1 : 0);
        mma_gemm_k<512, 4, true><<<dim3(cD / 128, cM / 128), 256>>>(
            qin, Rf, quw + (size_t)i * cD * cH, qub + (size_t)i * cD,
            qout, nullptr, qin, cD, 0);
        qin = qout;
    }

    ln_k<256><<<cM, 256>>>(Ac, olnw, olnb, Al);
    mma_gemm_k<256, 5, false><<<dim3(cD / 128, cM / 128), 256>>>(
        Al, nullptr, outw, outb, out, nullptr, x, cD, 0);
}

// round 7
// speedup vs baseline: 1.1340x; 1.1340x over previous
#include <cuda_runtime.h>
#include <cstdint>
#include <cstddef>
#include <math.h>

// Problem constants (fixed by setup_inputs)
constexpr int cB = 2, cL = 2048, cD = 256, cP = 16, cK = 4, cI = 3;
constexpr int cF = 32;
constexpr int cKD = 1024;
constexpr int cH = 512;
constexpr int cCH = 64;
constexpr int cNC = cL / cCH;
constexpr int cM = cB * cL;
#define PI_F 3.14159265358979323846f

// ---------------- scratch ---------------------------------------------------
__device__ float g_V[cM * cD];
__device__ float g_Mfeat[cB * cK * cL * cF];
__device__ float g_Qfeat[cB * cK * cL * cF];
__device__ float g_state[cB * cK * cNC * cF * cD];
__device__ float g_comb[cM * cKD];
__device__ float g_combln[cM * cKD];
__device__ float g_h[cM * cH];
__device__ float g_ref[cM * cD];
__device__ float g_acc[cM * cD];
__device__ float g_q0[cM * cD];
__device__ float g_q1[cM * cD];
__device__ float g_accln[cM * cD];

// ---------------- tf32 helpers ---------------------------------------------
__device__ __forceinline__ uint32_t f2tf(float x) {
    uint32_t r;
    asm("cvt.rna.tf32.f32 %0, %1;" : "=r"(r) : "f"(x));
    return r;
}
__device__ __forceinline__ void mma_tf32(float* c, const uint32_t* a, const uint32_t* b) {
    asm volatile(
        "mma.sync.aligned.m16n8k8.row.col.f32.tf32.tf32.f32 "
        "{%0,%1,%2,%3}, {%4,%5,%6,%7}, {%8,%9}, {%0,%1,%2,%3};\n"
        : "+f"(c[0]), "+f"(c[1]), "+f"(c[2]), "+f"(c[3])
        : "r"(a[0]), "r"(a[1]), "r"(a[2]), "r"(a[3]), "r"(b[0]), "r"(b[1]));
}
__device__ __forceinline__ void cp_async16(void* smem_dst, const void* gsrc) {
    uint32_t s = (uint32_t)__cvta_generic_to_shared(smem_dst);
    asm volatile("cp.async.cg.shared.global [%0], [%1], 16;\n" :: "r"(s), "l"(gsrc));
}

// ---------------- tf32 tensor-core GEMM, cp.async 3-stage pipelined --------
// C = epi(A @ W^T + bias). A: M x KDIM (SPLITA: [A|A2] each M x cD). W: N x KDIM.
// BM=128, BN=64, BK=16, 256 thr, warp grid 4(m) x 2(n), warp tile 32x32.
// Static smem: 3 stages x (128*20 + 64*20) floats = 46080 B (< 48 KB, no opt-in)
constexpr int GSA = 20;                  // padded row stride (floats)
constexpr int GS_A = 128 * GSA;          // floats per A stage
constexpr int GS_W = 64 * GSA;           // floats per W stage
constexpr int GS_STAGE = GS_A + GS_W;    // 3840 floats
constexpr int NSTAGE = 3;

template<int KDIM, int EPI, bool SPLITA>
__global__ __launch_bounds__(256) void mma_gemm_k(
    const float* __restrict__ A, const float* __restrict__ A2,
    const float* __restrict__ W, const float* __restrict__ bias,
    float* __restrict__ C, float* __restrict__ aux,
    const float* __restrict__ addsrc, int N, int flag)
{
    __shared__ float dsm[NSTAGE * GS_STAGE];
    const int tid = threadIdx.x;
    const int warp = tid >> 5, lane = tid & 31;
    const int wm = warp >> 1, wn = warp & 1;
    const int gid = lane >> 2, tig = lane & 3;
    const int m0 = blockIdx.y * 128;
    const int n0 = blockIdx.x * 64;
    const int lda = SPLITA ? cD : KDIM;
    constexpr int NK = KDIM / 16;

    auto issue_stage = [&](int s, int k0) {
        float* As = dsm + s * GS_STAGE;
        float* Ws = As + GS_A;
        const float* Ap = A;
        int kb = k0;
        if (SPLITA && k0 >= cD) { Ap = A2; kb = k0 - cD; }
        // A tile: 128 x 16 floats = 512 float4, 2 per thread
#pragma unroll
        for (int r = 0; r < 2; r++) {
            int idx4 = tid + r * 256;
            int mm = idx4 >> 2, q = idx4 & 3;
            cp_async16(&As[mm * GSA + q * 4],
                       &Ap[(size_t)(m0 + mm) * lda + kb + q * 4]);
        }
        // W tile: 64 x 16 floats = 256 float4, 1 per thread
        {
            int nn = tid >> 2, q = tid & 3;
            cp_async16(&Ws[nn * GSA + q * 4],
                       &W[(size_t)(n0 + nn) * KDIM + k0 + q * 4]);
        }
    };

    float acc[2][4][4];
#pragma unroll
    for (int i = 0; i < 2; i++)
#pragma unroll
        for (int j = 0; j < 4; j++)
#pragma unroll
            for (int r = 0; r < 4; r++) acc[i][j][r] = 0.f;

    // prefill stages 0..NSTAGE-2
#pragma unroll
    for (int p = 0; p < NSTAGE - 1; p++) {
        if (p < NK) issue_stage(p, p * 16);
        asm volatile("cp.async.commit_group;\n");
    }

    int ld_stage = NSTAGE - 1;
    for (int t = 0; t < NK; t++) {
        if (t + NSTAGE - 1 < NK) {
            issue_stage(ld_stage, (t + NSTAGE - 1) * 16);
            asm volatile("cp.async.commit_group;\n");
            ld_stage = (ld_stage + 1 == NSTAGE) ? 0 : ld_stage + 1;
            asm volatile("cp.async.wait_group 2;\n");
        } else if (t + NSTAGE - 2 < NK) {
            asm volatile("cp.async.wait_group 1;\n");
        } else {
            asm volatile("cp.async.wait_group 0;\n");
        }
        __syncthreads();
        int cs = t % NSTAGE;
        const float* As = dsm + cs * GS_STAGE;
        const float* Ws = As + GS_A;
#pragma unroll
        for (int ks = 0; ks < 2; ks++) {
            int kk = ks * 8;
            uint32_t a[2][4], b[4][2];
#pragma unroll
            for (int i = 0; i < 2; i++) {
                int mb = wm * 32 + i * 16;
                a[i][0] = __float_as_uint(As[(mb + gid) * GSA + kk + tig]);
                a[i][1] = __float_as_uint(As[(mb + gid + 8) * GSA + kk + tig]);
                a[i][2] = __float_as_uint(As[(mb + gid) * GSA + kk + tig + 4]);
                a[i][3] = __float_as_uint(As[(mb + gid + 8) * GSA + kk + tig + 4]);
            }
#pragma unroll
            for (int j = 0; j < 4; j++) {
                int nb = wn * 32 + j * 8;
                b[j][0] = __float_as_uint(Ws[(nb + gid) * GSA + kk + tig]);
                b[j][1] = __float_as_uint(Ws[(nb + gid) * GSA + kk + tig + 4]);
            }
#pragma unroll
            for (int i = 0; i < 2; i++)
#pragma unroll
                for (int j = 0; j < 4; j++) mma_tf32(acc[i][j], a[i], b[j]);
        }
        __syncthreads();
    }

#pragma unroll
    for (int i = 0; i < 2; i++)
#pragma unroll
        for (int j = 0; j < 4; j++)
#pragma unroll
            for (int r = 0; r < 4; r++) {
                int m = m0 + wm * 32 + i * 16 + gid + ((r >= 2) ? 8 : 0);
                int n = n0 + wn * 32 + j * 8 + tig * 2 + (r & 1);
                float v = acc[i][j][r] + bias[n];
                if constexpr (EPI == 0) {
                    C[(size_t)m * N + n] = v;
                } else if constexpr (EPI == 2) {
                    v = 0.5f * v * (1.f + erff(v * 0.7071067811865476f));
                    C[(size_t)m * N + n] = v;
                } else if constexpr (EPI == 3) {
                    size_t o = (size_t)m * N + n;
                    C[o] = v;
                    aux[o] = flag ? v : (aux[o] + v);
                } else if constexpr (EPI == 4) {
                    size_t o = (size_t)m * N + n;
                    C[o] = addsrc[o] + tanhf(v);
                } else if constexpr (EPI == 5) {
                    size_t o = (size_t)m * N + n;
                    C[o] = addsrc[o] + v;
                }
            }
}

// ---------------- fp32 phase GEMM, BM=32 for full-chip occupancy -----------
__global__ __launch_bounds__(256) void phase_gemm_k(
    const float* __restrict__ A, const float* __restrict__ W,
    const float* __restrict__ bias, float* __restrict__ C)
{
    __shared__ float As[32][17];
    __shared__ float Ws[64][17];
    const int tid = threadIdx.x;
    const int tx = tid & 15, ty = tid >> 4;
    const int m0 = blockIdx.x * 32;
    constexpr int KDIM = 256;

    float acc[2][4];
#pragma unroll
    for (int i = 0; i < 2; i++)
#pragma unroll
        for (int j = 0; j < 4; j++) acc[i][j] = 0.f;

    for (int k0 = 0; k0 < KDIM; k0 += 16) {
        if (tid < 128) {
            int mm = tid >> 2, q = tid & 3;
            float4 a4 = *reinterpret_cast<const float4*>(
                &A[(size_t)(m0 + mm) * KDIM + k0 + q * 4]);
            As[mm][q * 4 + 0] = a4.x; As[mm][q * 4 + 1] = a4.y;
            As[mm][q * 4 + 2] = a4.z; As[mm][q * 4 + 3] = a4.w;
        }
        {
            int nn = tid >> 2, q = tid & 3;
            float4 w4 = *reinterpret_cast<const float4*>(
                &W[(size_t)nn * KDIM + k0 + q * 4]);
            Ws[nn][q * 4 + 0] = w4.x; Ws[nn][q * 4 + 1] = w4.y;
            Ws[nn][q * 4 + 2] = w4.z; Ws[nn][q * 4 + 3] = w4.w;
        }
        __syncthreads();
#pragma unroll
        for (int kk = 0; kk < 16; kk++) {
            float ra[2], rb[4];
#pragma unroll
            for (int i = 0; i < 2; i++) ra[i] = As[ty * 2 + i][kk];
#pragma unroll
            for (int j = 0; j < 4; j++) rb[j] = Ws[tx * 4 + j][kk];
#pragma unroll
            for (int i = 0; i < 2; i++)
#pragma unroll
                for (int j = 0; j < 4; j++) acc[i][j] = fmaf(ra[i], rb[j], acc[i][j]);
        }
        __syncthreads();
    }

#pragma unroll
    for (int i = 0; i < 2; i++) {
        int m = m0 + ty * 2 + i;
#pragma unroll
        for (int j = 0; j < 4; j++) {
            int n = tx * 4 + j;
            float v = acc[i][j] + bias[n];
            float t = tanhf(v) * PI_F;
            float sn, cs;
            sincosf(t, &sn, &cs);
            int bb = m / cL, l = m % cL;
            int kbank = n >> 4, p = n & 15;
            size_t base = ((size_t)(bb * cK + kbank) * cL + l) * cF;
            C[base + p] = cs;
            C[base + cP + p] = sn;
        }
    }
}

// ------------- per-chunk feature^T @ V partial sums ------------------------
__global__ __launch_bounds__(256) void chunk_partial_k(
    const float* __restrict__ mfeat, const float* __restrict__ V,
    float* __restrict__ state)
{
    const int ci = blockIdx.x, bk = blockIdx.y;
    const int bb = bk >> 2, kk = bk & 3;
    const int d = threadIdx.x;
    __shared__ float sMf[cCH * cF];
    const size_t featBase = ((size_t)(bb * cK + kk) * cL + (size_t)ci * cCH) * cF;
    for (int r = 0; r < 8; r++) sMf[d + r * 256] = mfeat[featBase + d + r * 256];
    __syncthreads();
    float acc[cF];
#pragma unroll
    for (int f = 0; f < cF; f++) acc[f] = 0.f;
    const float* vp = V + ((size_t)(bb * cL) + (size_t)ci * cCH) * cD;
    for (int l = 0; l < cCH; l++) {
        float v = vp[(size_t)l * cD + d];
#pragma unroll
        for (int f = 0; f < cF; f++) acc[f] = fmaf(sMf[l * cF + f], v, acc[f]);
    }
    float* st = state + (((size_t)(bb * cK + kk) * cNC + ci) * cF) * cD + d;
#pragma unroll
    for (int f = 0; f < cF; f++) st[(size_t)f * cD] = acc[f];
}

// ------------- exclusive prefix scan of chunk states over ci ---------------
__global__ __launch_bounds__(256) void scan_k(float* __restrict__ state)
{
    int u = blockIdx.x * 256 + threadIdx.x;
    if (u >= cB * cK * cF * cD) return;
    int fd = u & (cF * cD - 1);
    int bk = u >> 13;
    float* base = state + (size_t)bk * cNC * cF * cD + fd;
    float run = 0.f;
    for (int ci = 0; ci < cNC; ci++) {
        float t = base[(size_t)ci * cF * cD];
        base[(size_t)ci * cF * cD] = run;
        run += t;
    }
}

// ------------- retrieval via tf32 mma: R = Qf@S + tril(Qf@Mf^T)@V ----------
__global__ __launch_bounds__(256) void retrieve_mma_k(
    const float* __restrict__ qfeat, const float* __restrict__ mfeat,
    const float* __restrict__ state, const float* __restrict__ V,
    float* __restrict__ comb)
{
    constexpr int SQ = 36;
    constexpr int SAs = 68;
    constexpr int SB = 72;
    __shared__ uint32_t sQ[64 * SQ];
    __shared__ uint32_t sA[64 * SAs];
    __shared__ uint32_t sB[64 * SB];

    const int ci = blockIdx.x;
    const int bk = blockIdx.y;
    const int bb = bk >> 2, kb = bk & 3;
    const int tid = threadIdx.x;
    const int warp = tid >> 5, lane = tid & 31;
    const int wm2 = warp >> 2, wn4 = warp & 3;
    const int gid = lane >> 2, tig = lane & 3;

    const size_t featBase = ((size_t)(bb * cK + kb) * cL + (size_t)ci * cCH) * cF;
#pragma unroll
    for (int r = 0; r < 2; r++) {
        int idx4 = tid + r * 256;
        int row = idx4 >> 3, q = idx4 & 7;
        float4 a4 = *reinterpret_cast<const float4*>(&qfeat[featBase + (size_t)row * cF + q * 4]);
        uint32_t* s = &sQ[row * SQ + q * 4];
        s[0] = f2tf(a4.x); s[1] = f2tf(a4.y); s[2] = f2tf(a4.z); s[3] = f2tf(a4.w);
        float4 m4 = *reinterpret_cast<const float4*>(&mfeat[featBase + (size_t)row * cF + q * 4]);
        uint32_t* t = &sB[row * SQ + q * 4];
        t[0] = f2tf(m4.x); t[1] = f2tf(m4.y); t[2] = f2tf(m4.z); t[3] = f2tf(m4.w);
    }
    __syncthreads();

    // A = tril(Qf @ Mf^T)
    {
        float accA[2][2][4];
#pragma unroll
        for (int i = 0; i < 2; i++)
#pragma unroll
            for (int j = 0; j < 2; j++)
#pragma unroll
                for (int r = 0; r < 4; r++) accA[i][j][r] = 0.f;
#pragma unroll
        for (int ks = 0; ks < 4; ks++) {
            int kk = ks * 8;
            uint32_t a[2][4], b[2][2];
#pragma unroll
            for (int i = 0; i < 2; i++) {
                int mb = wm2 * 32 + i * 16;
                a[i][0] = sQ[(mb + gid) * SQ + kk + tig];
                a[i][1] = sQ[(mb + gid + 8) * SQ + kk + tig];
                a[i][2] = sQ[(mb + gid) * SQ + kk + tig + 4];
                a[i][3] = sQ[(mb + gid + 8) * SQ + kk + tig + 4];
            }
#pragma unroll
            for (int j = 0; j < 2; j++) {
                int nb = wn4 * 16 + j * 8;
                b[j][0] = sB[(nb + gid) * SQ + kk + tig];
                b[j][1] = sB[(nb + gid) * SQ + kk + tig + 4];
            }
#pragma unroll
            for (int i = 0; i < 2; i++)
#pragma unroll
                for (int j = 0; j < 2; j++) mma_tf32(accA[i][j], a[i], b[j]);
        }
        __syncthreads();
#pragma unroll
        for (int i = 0; i < 2; i++)
#pragma unroll
            for (int j = 0; j < 2; j++)
#pragma unroll
                for (int r = 0; r < 4; r++) {
                    int m = wm2 * 32 + i * 16 + gid + ((r >= 2) ? 8 : 0);
                    int n = wn4 * 16 + j * 8 + tig * 2 + (r & 1);
                    float v = (n <= m) ? accA[i][j][r] : 0.f;
                    sA[m * SAs + n] = f2tf(v);
                }
    }
    __syncthreads();

    const size_t stBase = (((size_t)(bb * cK + kb) * cNC + ci) * cF) * cD;
    const size_t vBase = ((size_t)(bb * cL) + (size_t)ci * cCH) * cD;

    for (int dh = 0; dh < 4; dh++) {
        __syncthreads();
#pragma unroll
        for (int r = 0; r < 2; r++) {
            int idx4 = tid + r * 256;
            int f = idx4 >> 4, q = idx4 & 15;
            float4 s4 = *reinterpret_cast<const float4*>(&state[stBase + (size_t)f * cD + dh * 64 + q * 4]);
            uint32_t* s = &sB[f * SB + q * 4];
            s[0] = f2tf(s4.x); s[1] = f2tf(s4.y); s[2] = f2tf(s4.z); s[3] = f2tf(s4.w);
        }
        __syncthreads();

        float accO[2][2][4];
#pragma unroll
        for (int i = 0; i < 2; i++)
#pragma unroll
            for (int j = 0; j < 2; j++)
#pragma unroll
                for (int r = 0; r < 4; r++) accO[i][j][r] = 0.f;

#pragma unroll
        for (int ks = 0; ks < 4; ks++) {
            int kk = ks * 8;
            uint32_t a[2][4], b[2][2];
#pragma unroll
            for (int i = 0; i < 2; i++) {
                int mb = wm2 * 32 + i * 16;
                a[i][0] = sQ[(mb + gid) * SQ + kk + tig];
                a[i][1] = sQ[(mb + gid + 8) * SQ + kk + tig];
                a[i][2] = sQ[(mb + gid) * SQ + kk + tig + 4];
                a[i][3] = sQ[(mb + gid + 8) * SQ + kk + tig + 4];
            }
#pragma unroll
            for (int j = 0; j < 2; j++) {
                int nb = wn4 * 16 + j * 8;
                b[j][0] = sB[(kk + tig) * SB + nb + gid];
                b[j][1] = sB[(kk + tig + 4) * SB + nb + gid];
            }
#pragma unroll
            for (int i = 0; i < 2; i++)
#pragma unroll
                for (int j = 0; j < 2; j++) mma_tf32(accO[i][j], a[i], b[j]);
        }
        __syncthreads();
#pragma unroll
        for (int r = 0; r < 4; r++) {
            int idx4 = tid + r * 256;
            int row = idx4 >> 4, q = idx4 & 15;
            float4 v4 = *reinterpret_cast<const float4*>(&V[vBase + (size_t)row * cD + dh * 64 + q * 4]);
            uint32_t* s = &sB[row * SB + q * 4];
            s[0] = f2tf(v4.x); s[1] = f2tf(v4.y); s[2] = f2tf(v4.z); s[3] = f2tf(v4.w);
        }
        __syncthreads();

#pragma unroll
        for (int ks = 0; ks < 8; ks++) {
            int kk = ks * 8;
            uint32_t a[2][4], b[2][2];
#pragma unroll
            for (int i = 0; i < 2; i++) {
                int mb = wm2 * 32 + i * 16;
                a[i][0] = sA[(mb + gid) * SAs + kk + tig];
                a[i][1] = sA[(mb + gid + 8) * SAs + kk + tig];
                a[i][2] = sA[(mb + gid) * SAs + kk + tig + 4];
                a[i][3] = sA[(mb + gid + 8) * SAs + kk + tig + 4];
            }
#pragma unroll
            for (int j = 0; j < 2; j++) {
                int nb = wn4 * 16 + j * 8;
                b[j][0] = sB[(kk + tig) * SB + nb + gid];
                b[j][1] = sB[(kk + tig + 4) * SB + nb + gid];
            }
#pragma unroll
            for (int i = 0; i < 2; i++)
#pragma unroll
                for (int j = 0; j < 2; j++) mma_tf32(accO[i][j], a[i], b[j]);
        }

#pragma unroll
        for (int i = 0; i < 2; i++)
#pragma unroll
            for (int j = 0; j < 2; j++)
#pragma unroll
                for (int r = 0; r < 4; r++) {
                    int ml = wm2 * 32 + i * 16 + gid + ((r >= 2) ? 8 : 0);
                    int nl = wn4 * 16 + j * 8 + tig * 2 + (r & 1);
                    int l = ci * cCH + ml;
                    float sc = rsqrtf(16.f * (float)(l + 1));
                    comb[((size_t)(bb * cL + l)) * cKD + (size_t)kb * cD + dh * 64 + nl] =
                        accO[i][j][r] * sc;
                }
    }
}

// ------------- row LayerNorm ------------------------------------------------
template<int NDIM>
__global__ __launch_bounds__(256) void ln_k(
    const float* __restrict__ in, const float* __restrict__ w,
    const float* __restrict__ bsh, float* __restrict__ out)
{
    const int row = blockIdx.x;
    const float* xp = in + (size_t)row * NDIM;
    constexpr int R = NDIM / 256;
    float vals[R];
    float s = 0.f, s2 = 0.f;
#pragma unroll
    for (int r = 0; r < R; r++) {
        float v = xp[threadIdx.x + r * 256];
        vals[r] = v; s += v; s2 += v * v;
    }
#pragma unroll
    for (int o = 16; o > 0; o >>= 1) {
        s += __shfl_xor_sync(0xffffffffu, s, o);
        s2 += __shfl_xor_sync(0xffffffffu, s2, o);
    }
    __shared__ float rs[8], rs2[8], sm[2];
    int wid = threadIdx.x >> 5, lane = threadIdx.x & 31;
    if (lane == 0) { rs[wid] = s; rs2[wid] = s2; }
    __syncthreads();
    if (threadIdx.x == 0) {
        float a = 0.f, c = 0.f;
        for (int i = 0; i < 8; i++) { a += rs[i]; c += rs2[i]; }
        float mean = a / NDIM;
        float var = c / NDIM - mean * mean;
        sm[0] = mean;
        sm[1] = rsqrtf(fmaxf(var, 0.f) + 1e-5f);
    }
    __syncthreads();
    float mean = sm[0], inv = sm[1];
    float* op = out + (size_t)row * NDIM;
#pragma unroll
    for (int r = 0; r < R; r++) {
        int i = threadIdx.x + r * 256;
        op[i] = (vals[r] - mean) * inv * w[i] + bsh[i];
    }
}

// ------------- host orchestration ------------------------------------------
extern "C" void kernel_launch(void* const* d_in, const int* in_sizes, int n_in,
                              void* d_out, int out_size)
{
    const float* x       = (const float*)d_in[0];
    const float* phase_w = (const float*)d_in[1];
    const float* phase_b = (const float*)d_in[2];
    const float* val_w   = (const float*)d_in[3];
    const float* val_b   = (const float*)d_in[4];
    const float* rlnw    = (const float*)d_in[5];
    const float* rlnb    = (const float*)d_in[6];
    const float* r1w     = (const float*)d_in[7];
    const float* r1b     = (const float*)d_in[8];
    const float* r2w     = (const float*)d_in[9];
    const float* r2b     = (const float*)d_in[10];
    const float* quw     = (const float*)d_in[11];
    const float* qub     = (const float*)d_in[12];
    const float* olnw    = (const float*)d_in[13];
    const float* olnb    = (const float*)d_in[14];
    const float* outw    = (const float*)d_in[15];
    const float* outb    = (const float*)d_in[16];
    float* out = (float*)d_out;

    float *V, *Mf, *Qf, *St, *Cb, *Cl, *Hh, *Rf, *Ac, *Q0, *Q1, *Al;
    cudaGetSymbolAddress((void**)&V,  g_V);
    cudaGetSymbolAddress((void**)&Mf, g_Mfeat);
    cudaGetSymbolAddress((void**)&Qf, g_Qfeat);
    cudaGetSymbolAddress((void**)&St, g_state);
    cudaGetSymbolAddress((void**)&Cb, g_comb);
    cudaGetSymbolAddress((void**)&Cl, g_combln);
    cudaGetSymbolAddress((void**)&Hh, g_h);
    cudaGetSymbolAddress((void**)&Rf, g_ref);
    cudaGetSymbolAddress((void**)&Ac, g_acc);
    cudaGetSymbolAddress((void**)&Q0, g_q0);
    cudaGetSymbolAddress((void**)&Q1, g_q1);
    cudaGetSymbolAddress((void**)&Al, g_accln);

    // values GEMM (tf32 mma): (4096x256) @ (256x256)^T
    mma_gemm_k<256, 0, false><<<dim3(cD / 64, cM / 128), 256>>>(
        x, nullptr, val_w, val_b, V, nullptr, nullptr, cD, 0);
    // memory-side phase features (fp32)
    phase_gemm_k<<<cM / 32, 256>>>(x, phase_w, phase_b, Mf);
    chunk_partial_k<<<dim3(cNC, cB * cK), 256>>>(Mf, V, St);
    scan_k<<<256, 256>>>(St);

    const float* qin = x;
    for (int i = 0; i < cI; i++) {
        float* qout = (i & 1) ? Q1 : Q0;
        phase_gemm_k<<<cM / 32, 256>>>(qin, phase_w, phase_b, Qf);
        retrieve_mma_k<<<dim3(cNC, cB * cK), 256>>>(Qf, Mf, St, V, Cb);
        ln_k<1024><<<cM, 256>>>(Cb, rlnw + (size_t)i * cKD, rlnb + (size_t)i * cKD, Cl);
        mma_gemm_k<1024, 2, false><<<dim3(cH / 64, cM / 128), 256>>>(
            Cl, nullptr, r1w + (size_t)i * cH * cKD, r1b + (size_t)i * cH,
            Hh, nullptr, nullptr, cH, 0);
        mma_gemm_k<512, 3, false><<<dim3(cD / 64, cM / 128), 256>>>(
            Hh, nullptr, r2w + (size_t)i * cD * cH, r2b + (size_t)i * cD,
            Rf, Ac, nullptr, cD, (i == 0) ? 1 : 0);
        mma_gemm_k<512, 4, true><<<dim3(cD / 64, cM / 128), 256>>>(
            qin, Rf, quw + (size_t)i * cD * cH, qub + (size_t)i * cD,
            qout, nullptr, qin, cD, 0);
        qin = qout;
    }

    ln_k<256><<<cM, 256>>>(Ac, olnw, olnb, Al);
    mma_gemm_k<256, 5, false><<<dim3(cD / 64, cM / 128), 256>>>(
        Al, nullptr, outw, outb, out, nullptr, x, cD, 0);
}

// round 8
// speedup vs baseline: 1.4669x; 1.2936x over previous
#include <cuda_runtime.h>
#include <cuda_fp16.h>
#include <cstdint>
#include <cstddef>
#include <math.h>

// Problem constants (fixed by setup_inputs)
constexpr int cB = 2, cL = 2048, cD = 256, cP = 16, cK = 4, cI = 3;
constexpr int cF = 32;
constexpr int cKD = 1024;
constexpr int cH = 512;
constexpr int cCH = 64;
constexpr int cNC = cL / cCH;
constexpr int cM = cB * cL;
#define PI_F 3.14159265358979323846f

// ---------------- scratch ---------------------------------------------------
__device__ float g_V[cM * cD];
__device__ float g_Mfeat[cB * cK * cL * cF];
__device__ float g_Qfeat[cB * cK * cL * cF];
__device__ float g_state[cB * cK * cNC * cF * cD];
__device__ float g_comb[cM * cKD];
__device__ float g_ref[cM * cD];           // unused fp32 refined (kept for safety)
__device__ float g_acc[cM * cD];
__device__ float g_q0[cM * cD];
__device__ float g_q1[cM * cD];
// half activation buffers
__device__ __half g_xh[cM * cD];
__device__ __half g_Clh[cM * cKD];
__device__ __half g_Hhh[cM * cH];
__device__ __half g_Rfh[cM * cD];
__device__ __half g_q0h[cM * cD];
__device__ __half g_q1h[cM * cD];
__device__ __half g_Alh[cM * cD];
// half weights
__device__ __half g_valwh[cD * cD];
__device__ __half g_r1wh[cI * cH * cKD];
__device__ __half g_r2wh[cI * cD * cH];
__device__ __half g_quwh[cI * cD * cH];
__device__ __half g_outwh[cD * cD];

// ---------------- helpers ---------------------------------------------------
__device__ __forceinline__ uint32_t f2tf(float x) {
    uint32_t r;
    asm("cvt.rna.tf32.f32 %0, %1;" : "=r"(r) : "f"(x));
    return r;
}
__device__ __forceinline__ void mma_tf32(float* c, const uint32_t* a, const uint32_t* b) {
    asm volatile(
        "mma.sync.aligned.m16n8k8.row.col.f32.tf32.tf32.f32 "
        "{%0,%1,%2,%3}, {%4,%5,%6,%7}, {%8,%9}, {%0,%1,%2,%3};\n"
        : "+f"(c[0]), "+f"(c[1]), "+f"(c[2]), "+f"(c[3])
        : "r"(a[0]), "r"(a[1]), "r"(a[2]), "r"(a[3]), "r"(b[0]), "r"(b[1]));
}
__device__ __forceinline__ void mma_f16(float* c, const uint32_t* a, const uint32_t* b) {
    asm volatile(
        "mma.sync.aligned.m16n8k16.row.col.f32.f16.f16.f32 "
        "{%0,%1,%2,%3}, {%4,%5,%6,%7}, {%8,%9}, {%0,%1,%2,%3};\n"
        : "+f"(c[0]), "+f"(c[1]), "+f"(c[2]), "+f"(c[3])
        : "r"(a[0]), "r"(a[1]), "r"(a[2]), "r"(a[3]), "r"(b[0]), "r"(b[1]));
}
__device__ __forceinline__ void cp_async16(void* smem_dst, const void* gsrc) {
    uint32_t s = (uint32_t)__cvta_generic_to_shared(smem_dst);
    asm volatile("cp.async.cg.shared.global [%0], [%1], 16;\n" :: "r"(s), "l"(gsrc));
}

// ---------------- weight / x fp32->fp16 conversion (once per call) ----------
__global__ __launch_bounds__(256) void cvt_h_k(
    const float* __restrict__ val_w, const float* __restrict__ r1w,
    const float* __restrict__ r2w, const float* __restrict__ quw,
    const float* __restrict__ outw, const float* __restrict__ x)
{
    int gsz = gridDim.x * blockDim.x;
    int t0 = blockIdx.x * blockDim.x + threadIdx.x;
    for (int i = t0; i < cD * cD; i += gsz) g_valwh[i] = __float2half(val_w[i]);
    for (int i = t0; i < cI * cH * cKD; i += gsz) g_r1wh[i] = __float2half(r1w[i]);
    for (int i = t0; i < cI * cD * cH; i += gsz) g_r2wh[i] = __float2half(r2w[i]);
    for (int i = t0; i < cI * cD * cH; i += gsz) g_quwh[i] = __float2half(quw[i]);
    for (int i = t0; i < cD * cD; i += gsz) g_outwh[i] = __float2half(outw[i]);
    for (int i = t0; i < cM * cD; i += gsz) g_xh[i] = __float2half(x[i]);
}

// ---------------- fp16 tensor-core GEMM, cp.async 3-stage -------------------
// C = epi(A @ W^T + bias). A: M x KDIM half (SPLITA: [A|A2] each M x cD).
// W: N x KDIM half. BM=128, BN=64, BK=32, 256 thr, 4x2 warps, 32x32 warp tile.
// Static smem: 3 stages x (128*40 + 64*40) halves = 46080 B
constexpr int GSH = 40;                  // padded row stride (halves)
constexpr int GS_A = 128 * GSH;
constexpr int GS_W = 64 * GSH;
constexpr int GS_STAGE = GS_A + GS_W;    // 7680 halves
constexpr int NSTAGE = 3;

// EPI: 0 f32 out | 2 gelu->half | 3 refined->half + acc f32 | 4 gate | 5 final
template<int KDIM, int EPI, bool SPLITA>
__global__ __launch_bounds__(256) void mma_gemm_k(
    const __half* __restrict__ A, const __half* __restrict__ A2,
    const __half* __restrict__ W, const float* __restrict__ bias,
    float* __restrict__ C, __half* __restrict__ Ch, float* __restrict__ aux,
    const float* __restrict__ addsrc, int N, int flag)
{
    __shared__ __half dsm[NSTAGE * GS_STAGE];
    const int tid = threadIdx.x;
    const int warp = tid >> 5, lane = tid & 31;
    const int wm = warp >> 1, wn = warp & 1;
    const int gid = lane >> 2, tig = lane & 3;
    const int m0 = blockIdx.y * 128;
    const int n0 = blockIdx.x * 64;
    const int lda = SPLITA ? cD : KDIM;
    constexpr int NK = KDIM / 32;

    auto issue_stage = [&](int s, int k0) {
        __half* As = dsm + s * GS_STAGE;
        __half* Ws = As + GS_A;
        const __half* Ap = A;
        int kb = k0;
        if (SPLITA && k0 >= cD) { Ap = A2; kb = k0 - cD; }
        // A tile: 128 x 32 halves = 8192 B = 512 x 16B, 2 per thread
#pragma unroll
        for (int r = 0; r < 2; r++) {
            int idx = tid + r * 256;
            int mm = idx >> 2, q = idx & 3;
            cp_async16(&As[mm * GSH + q * 8],
                       &Ap[(size_t)(m0 + mm) * lda + kb + q * 8]);
        }
        // W tile: 64 x 32 halves = 4096 B = 256 x 16B, 1 per thread
        {
            int nn = tid >> 2, q = tid & 3;
            cp_async16(&Ws[nn * GSH + q * 8],
                       &W[(size_t)(n0 + nn) * KDIM + k0 + q * 8]);
        }
    };

    float acc[2][4][4];
#pragma unroll
    for (int i = 0; i < 2; i++)
#pragma unroll
        for (int j = 0; j < 4; j++)
#pragma unroll
            for (int r = 0; r < 4; r++) acc[i][j][r] = 0.f;

#pragma unroll
    for (int p = 0; p < NSTAGE - 1; p++) {
        if (p < NK) issue_stage(p, p * 32);
        asm volatile("cp.async.commit_group;\n");
    }

    int ld_stage = NSTAGE - 1;
    for (int t = 0; t < NK; t++) {
        if (t + NSTAGE - 1 < NK) {
            issue_stage(ld_stage, (t + NSTAGE - 1) * 32);
            asm volatile("cp.async.commit_group;\n");
            ld_stage = (ld_stage + 1 == NSTAGE) ? 0 : ld_stage + 1;
            asm volatile("cp.async.wait_group 2;\n");
        } else if (t + NSTAGE - 2 < NK) {
            asm volatile("cp.async.wait_group 1;\n");
        } else {
            asm volatile("cp.async.wait_group 0;\n");
        }
        __syncthreads();
        int cs = t % NSTAGE;
        const __half* As = dsm + cs * GS_STAGE;
        const __half* Ws = As + GS_A;
#pragma unroll
        for (int ks = 0; ks < 2; ks++) {
            int kk = ks * 16;
            uint32_t a[2][4], b[4][2];
#pragma unroll
            for (int i = 0; i < 2; i++) {
                int mb = wm * 32 + i * 16;
                a[i][0] = *(const uint32_t*)&As[(mb + gid) * GSH + kk + tig * 2];
                a[i][1] = *(const uint32_t*)&As[(mb + gid + 8) * GSH + kk + tig * 2];
                a[i][2] = *(const uint32_t*)&As[(mb + gid) * GSH + kk + tig * 2 + 8];
                a[i][3] = *(const uint32_t*)&As[(mb + gid + 8) * GSH + kk + tig * 2 + 8];
            }
#pragma unroll
            for (int j = 0; j < 4; j++) {
                int nb = wn * 32 + j * 8;
                b[j][0] = *(const uint32_t*)&Ws[(nb + gid) * GSH + kk + tig * 2];
                b[j][1] = *(const uint32_t*)&Ws[(nb + gid) * GSH + kk + tig * 2 + 8];
            }
#pragma unroll
            for (int i = 0; i < 2; i++)
#pragma unroll
                for (int j = 0; j < 4; j++) mma_f16(acc[i][j], a[i], b[j]);
        }
        __syncthreads();
    }

#pragma unroll
    for (int i = 0; i < 2; i++)
#pragma unroll
        for (int j = 0; j < 4; j++)
#pragma unroll
            for (int r = 0; r < 4; r++) {
                int m = m0 + wm * 32 + i * 16 + gid + ((r >= 2) ? 8 : 0);
                int n = n0 + wn * 32 + j * 8 + tig * 2 + (r & 1);
                float v = acc[i][j][r] + bias[n];
                size_t o = (size_t)m * N + n;
                if constexpr (EPI == 0) {
                    C[o] = v;
                } else if constexpr (EPI == 2) {
                    v = 0.5f * v * (1.f + erff(v * 0.7071067811865476f));
                    Ch[o] = __float2half(v);
                } else if constexpr (EPI == 3) {
                    Ch[o] = __float2half(v);
                    aux[o] = flag ? v : (aux[o] + v);
                } else if constexpr (EPI == 4) {
                    float q = addsrc[o] + tanhf(v);
                    C[o] = q;
                    Ch[o] = __float2half(q);
                } else if constexpr (EPI == 5) {
                    C[o] = addsrc[o] + v;
                }
            }
}

// ---------------- fp32 phase GEMM, BM=32 for full-chip occupancy -----------
__global__ __launch_bounds__(256) void phase_gemm_k(
    const float* __restrict__ A, const float* __restrict__ W,
    const float* __restrict__ bias, float* __restrict__ C)
{
    __shared__ float As[32][17];
    __shared__ float Ws[64][17];
    const int tid = threadIdx.x;
    const int tx = tid & 15, ty = tid >> 4;
    const int m0 = blockIdx.x * 32;
    constexpr int KDIM = 256;

    float acc[2][4];
#pragma unroll
    for (int i = 0; i < 2; i++)
#pragma unroll
        for (int j = 0; j < 4; j++) acc[i][j] = 0.f;

    for (int k0 = 0; k0 < KDIM; k0 += 16) {
        if (tid < 128) {
            int mm = tid >> 2, q = tid & 3;
            float4 a4 = *reinterpret_cast<const float4*>(
                &A[(size_t)(m0 + mm) * KDIM + k0 + q * 4]);
            As[mm][q * 4 + 0] = a4.x; As[mm][q * 4 + 1] = a4.y;
            As[mm][q * 4 + 2] = a4.z; As[mm][q * 4 + 3] = a4.w;
        }
        {
            int nn = tid >> 2, q = tid & 3;
            float4 w4 = *reinterpret_cast<const float4*>(
                &W[(size_t)nn * KDIM + k0 + q * 4]);
            Ws[nn][q * 4 + 0] = w4.x; Ws[nn][q * 4 + 1] = w4.y;
            Ws[nn][q * 4 + 2] = w4.z; Ws[nn][q * 4 + 3] = w4.w;
        }
        __syncthreads();
#pragma unroll
        for (int kk = 0; kk < 16; kk++) {
            float ra[2], rb[4];
#pragma unroll
            for (int i = 0; i < 2; i++) ra[i] = As[ty * 2 + i][kk];
#pragma unroll
            for (int j = 0; j < 4; j++) rb[j] = Ws[tx * 4 + j][kk];
#pragma unroll
            for (int i = 0; i < 2; i++)
#pragma unroll
                for (int j = 0; j < 4; j++) acc[i][j] = fmaf(ra[i], rb[j], acc[i][j]);
        }
        __syncthreads();
    }

#pragma unroll
    for (int i = 0; i < 2; i++) {
        int m = m0 + ty * 2 + i;
#pragma unroll
        for (int j = 0; j < 4; j++) {
            int n = tx * 4 + j;
            float v = acc[i][j] + bias[n];
            float t = tanhf(v) * PI_F;
            float sn, cs;
            sincosf(t, &sn, &cs);
            int bb = m / cL, l = m % cL;
            int kbank = n >> 4, p = n & 15;
            size_t base = ((size_t)(bb * cK + kbank) * cL + l) * cF;
            C[base + p] = cs;
            C[base + cP + p] = sn;
        }
    }
}

// ------------- per-chunk feature^T @ V partial sums ------------------------
__global__ __launch_bounds__(256) void chunk_partial_k(
    const float* __restrict__ mfeat, const float* __restrict__ V,
    float* __restrict__ state)
{
    const int ci = blockIdx.x, bk = blockIdx.y;
    const int bb = bk >> 2, kk = bk & 3;
    const int d = threadIdx.x;
    __shared__ float sMf[cCH * cF];
    const size_t featBase = ((size_t)(bb * cK + kk) * cL + (size_t)ci * cCH) * cF;
    for (int r = 0; r < 8; r++) sMf[d + r * 256] = mfeat[featBase + d + r * 256];
    __syncthreads();
    float acc[cF];
#pragma unroll
    for (int f = 0; f < cF; f++) acc[f] = 0.f;
    const float* vp = V + ((size_t)(bb * cL) + (size_t)ci * cCH) * cD;
    for (int l = 0; l < cCH; l++) {
        float v = vp[(size_t)l * cD + d];
#pragma unroll
        for (int f = 0; f < cF; f++) acc[f] = fmaf(sMf[l * cF + f], v, acc[f]);
    }
    float* st = state + (((size_t)(bb * cK + kk) * cNC + ci) * cF) * cD + d;
#pragma unroll
    for (int f = 0; f < cF; f++) st[(size_t)f * cD] = acc[f];
}

// ------------- exclusive prefix scan of chunk states over ci ---------------
__global__ __launch_bounds__(256) void scan_k(float* __restrict__ state)
{
    int u = blockIdx.x * 256 + threadIdx.x;
    if (u >= cB * cK * cF * cD) return;
    int fd = u & (cF * cD - 1);
    int bk = u >> 13;
    float* base = state + (size_t)bk * cNC * cF * cD + fd;
    float run = 0.f;
    for (int ci = 0; ci < cNC; ci++) {
        float t = base[(size_t)ci * cF * cD];
        base[(size_t)ci * cF * cD] = run;
        run += t;
    }
}

// ------------- retrieval via tf32 mma: R = Qf@S + tril(Qf@Mf^T)@V ----------
__global__ __launch_bounds__(256) void retrieve_mma_k(
    const float* __restrict__ qfeat, const float* __restrict__ mfeat,
    const float* __restrict__ state, const float* __restrict__ V,
    float* __restrict__ comb)
{
    constexpr int SQ = 36;
    constexpr int SAs = 68;
    constexpr int SB = 72;
    __shared__ uint32_t sQ[64 * SQ];
    __shared__ uint32_t sA[64 * SAs];
    __shared__ uint32_t sB[64 * SB];

    const int ci = blockIdx.x;
    const int bk = blockIdx.y;
    const int bb = bk >> 2, kb = bk & 3;
    const int tid = threadIdx.x;
    const int warp = tid >> 5, lane = tid & 31;
    const int wm2 = warp >> 2, wn4 = warp & 3;
    const int gid = lane >> 2, tig = lane & 3;

    const size_t featBase = ((size_t)(bb * cK + kb) * cL + (size_t)ci * cCH) * cF;
#pragma unroll
    for (int r = 0; r < 2; r++) {
        int idx4 = tid + r * 256;
        int row = idx4 >> 3, q = idx4 & 7;
        float4 a4 = *reinterpret_cast<const float4*>(&qfeat[featBase + (size_t)row * cF + q * 4]);
        uint32_t* s = &sQ[row * SQ + q * 4];
        s[0] = f2tf(a4.x); s[1] = f2tf(a4.y); s[2] = f2tf(a4.z); s[3] = f2tf(a4.w);
        float4 m4 = *reinterpret_cast<const float4*>(&mfeat[featBase + (size_t)row * cF + q * 4]);
        uint32_t* t = &sB[row * SQ + q * 4];
        t[0] = f2tf(m4.x); t[1] = f2tf(m4.y); t[2] = f2tf(m4.z); t[3] = f2tf(m4.w);
    }
    __syncthreads();

    // A = tril(Qf @ Mf^T)
    {
        float accA[2][2][4];
#pragma unroll
        for (int i = 0; i < 2; i++)
#pragma unroll
            for (int j = 0; j < 2; j++)
#pragma unroll
                for (int r = 0; r < 4; r++) accA[i][j][r] = 0.f;
#pragma unroll
        for (int ks = 0; ks < 4; ks++) {
            int kk = ks * 8;
            uint32_t a[2][4], b[2][2];
#pragma unroll
            for (int i = 0; i < 2; i++) {
                int mb = wm2 * 32 + i * 16;
                a[i][0] = sQ[(mb + gid) * SQ + kk + tig];
                a[i][1] = sQ[(mb + gid + 8) * SQ + kk + tig];
                a[i][2] = sQ[(mb + gid) * SQ + kk + tig + 4];
                a[i][3] = sQ[(mb + gid + 8) * SQ + kk + tig + 4];
            }
#pragma unroll
            for (int j = 0; j < 2; j++) {
                int nb = wn4 * 16 + j * 8;
                b[j][0] = sB[(nb + gid) * SQ + kk + tig];
                b[j][1] = sB[(nb + gid) * SQ + kk + tig + 4];
            }
#pragma unroll
            for (int i = 0; i < 2; i++)
#pragma unroll
                for (int j = 0; j < 2; j++) mma_tf32(accA[i][j], a[i], b[j]);
        }
        __syncthreads();
#pragma unroll
        for (int i = 0; i < 2; i++)
#pragma unroll
            for (int j = 0; j < 2; j++)
#pragma unroll
                for (int r = 0; r < 4; r++) {
                    int m = wm2 * 32 + i * 16 + gid + ((r >= 2) ? 8 : 0);
                    int n = wn4 * 16 + j * 8 + tig * 2 + (r & 1);
                    float v = (n <= m) ? accA[i][j][r] : 0.f;
                    sA[m * SAs + n] = f2tf(v);
                }
    }
    __syncthreads();

    const size_t stBase = (((size_t)(bb * cK + kb) * cNC + ci) * cF) * cD;
    const size_t vBase = ((size_t)(bb * cL) + (size_t)ci * cCH) * cD;

    for (int dh = 0; dh < 4; dh++) {
        __syncthreads();
#pragma unroll
        for (int r = 0; r < 2; r++) {
            int idx4 = tid + r * 256;
            int f = idx4 >> 4, q = idx4 & 15;
            float4 s4 = *reinterpret_cast<const float4*>(&state[stBase + (size_t)f * cD + dh * 64 + q * 4]);
            uint32_t* s = &sB[f * SB + q * 4];
            s[0] = f2tf(s4.x); s[1] = f2tf(s4.y); s[2] = f2tf(s4.z); s[3] = f2tf(s4.w);
        }
        __syncthreads();

        float accO[2][2][4];
#pragma unroll
        for (int i = 0; i < 2; i++)
#pragma unroll
            for (int j = 0; j < 2; j++)
#pragma unroll
                for (int r = 0; r < 4; r++) accO[i][j][r] = 0.f;

#pragma unroll
        for (int ks = 0; ks < 4; ks++) {
            int kk = ks * 8;
            uint32_t a[2][4], b[2][2];
#pragma unroll
            for (int i = 0; i < 2; i++) {
                int mb = wm2 * 32 + i * 16;
                a[i][0] = sQ[(mb + gid) * SQ + kk + tig];
                a[i][1] = sQ[(mb + gid + 8) * SQ + kk + tig];
                a[i][2] = sQ[(mb + gid) * SQ + kk + tig + 4];
                a[i][3] = sQ[(mb + gid + 8) * SQ + kk + tig + 4];
            }
#pragma unroll
            for (int j = 0; j < 2; j++) {
                int nb = wn4 * 16 + j * 8;
                b[j][0] = sB[(kk + tig) * SB + nb + gid];
                b[j][1] = sB[(kk + tig + 4) * SB + nb + gid];
            }
#pragma unroll
            for (int i = 0; i < 2; i++)
#pragma unroll
                for (int j = 0; j < 2; j++) mma_tf32(accO[i][j], a[i], b[j]);
        }
        __syncthreads();
#pragma unroll
        for (int r = 0; r < 4; r++) {
            int idx4 = tid + r * 256;
            int row = idx4 >> 4, q = idx4 & 15;
            float4 v4 = *reinterpret_cast<const float4*>(&V[vBase + (size_t)row * cD + dh * 64 + q * 4]);
            uint32_t* s = &sB[row * SB + q * 4];
            s[0] = f2tf(v4.x); s[1] = f2tf(v4.y); s[2] = f2tf(v4.z); s[3] = f2tf(v4.w);
        }
        __syncthreads();

#pragma unroll
        for (int ks = 0; ks < 8; ks++) {
            int kk = ks * 8;
            uint32_t a[2][4], b[2][2];
#pragma unroll
            for (int i = 0; i < 2; i++) {
                int mb = wm2 * 32 + i * 16;
                a[i][0] = sA[(mb + gid) * SAs + kk + tig];
                a[i][1] = sA[(mb + gid + 8) * SAs + kk + tig];
                a[i][2] = sA[(mb + gid) * SAs + kk + tig + 4];
                a[i][3] = sA[(mb + gid + 8) * SAs + kk + tig + 4];
            }
#pragma unroll
            for (int j = 0; j < 2; j++) {
                int nb = wn4 * 16 + j * 8;
                b[j][0] = sB[(kk + tig) * SB + nb + gid];
                b[j][1] = sB[(kk + tig + 4) * SB + nb + gid];
            }
#pragma unroll
            for (int i = 0; i < 2; i++)
#pragma unroll
                for (int j = 0; j < 2; j++) mma_tf32(accO[i][j], a[i], b[j]);
        }

#pragma unroll
        for (int i = 0; i < 2; i++)
#pragma unroll
            for (int j = 0; j < 2; j++)
#pragma unroll
                for (int r = 0; r < 4; r++) {
                    int ml = wm2 * 32 + i * 16 + gid + ((r >= 2) ? 8 : 0);
                    int nl = wn4 * 16 + j * 8 + tig * 2 + (r & 1);
                    int l = ci * cCH + ml;
                    float sc = rsqrtf(16.f * (float)(l + 1));
                    comb[((size_t)(bb * cL + l)) * cKD + (size_t)kb * cD + dh * 64 + nl] =
                        accO[i][j][r] * sc;
                }
    }
}

// ------------- row LayerNorm (fp32 in, half out) ----------------------------
template<int NDIM>
__global__ __launch_bounds__(256) void ln_h_k(
    const float* __restrict__ in, const float* __restrict__ w,
    const float* __restrict__ bsh, __half* __restrict__ out)
{
    const int row = blockIdx.x;
    const float* xp = in + (size_t)row * NDIM;
    constexpr int R = NDIM / 256;
    float vals[R];
    float s = 0.f, s2 = 0.f;
#pragma unroll
    for (int r = 0; r < R; r++) {
        float v = xp[threadIdx.x + r * 256];
        vals[r] = v; s += v; s2 += v * v;
    }
#pragma unroll
    for (int o = 16; o > 0; o >>= 1) {
        s += __shfl_xor_sync(0xffffffffu, s, o);
        s2 += __shfl_xor_sync(0xffffffffu, s2, o);
    }
    __shared__ float rs[8], rs2[8], sm[2];
    int wid = threadIdx.x >> 5, lane = threadIdx.x & 31;
    if (lane == 0) { rs[wid] = s; rs2[wid] = s2; }
    __syncthreads();
    if (threadIdx.x == 0) {
        float a = 0.f, c = 0.f;
        for (int i = 0; i < 8; i++) { a += rs[i]; c += rs2[i]; }
        float mean = a / NDIM;
        float var = c / NDIM - mean * mean;
        sm[0] = mean;
        sm[1] = rsqrtf(fmaxf(var, 0.f) + 1e-5f);
    }
    __syncthreads();
    float mean = sm[0], inv = sm[1];
    __half* op = out + (size_t)row * NDIM;
#pragma unroll
    for (int r = 0; r < R; r++) {
        int i = threadIdx.x + r * 256;
        op[i] = __float2half((vals[r] - mean) * inv * w[i] + bsh[i]);
    }
}

// ------------- host orchestration ------------------------------------------
extern "C" void kernel_launch(void* const* d_in, const int* in_sizes, int n_in,
                              void* d_out, int out_size)
{
    const float* x       = (const float*)d_in[0];
    const float* phase_w = (const float*)d_in[1];
    const float* phase_b = (const float*)d_in[2];
    const float* val_w   = (const float*)d_in[3];
    const float* val_b   = (const float*)d_in[4];
    const float* rlnw    = (const float*)d_in[5];
    const float* rlnb    = (const float*)d_in[6];
    const float* r1w     = (const float*)d_in[7];
    const float* r1b     = (const float*)d_in[8];
    const float* r2w     = (const float*)d_in[9];
    const float* r2b     = (const float*)d_in[10];
    const float* quw     = (const float*)d_in[11];
    const float* qub     = (const float*)d_in[12];
    const float* olnw    = (const float*)d_in[13];
    const float* olnb    = (const float*)d_in[14];
    const float* outw    = (const float*)d_in[15];
    const float* outb    = (const float*)d_in[16];
    float* out = (float*)d_out;

    float *V, *Mf, *Qf, *St, *Cb, *Ac, *Q0, *Q1;
    cudaGetSymbolAddress((void**)&V,  g_V);
    cudaGetSymbolAddress((void**)&Mf, g_Mfeat);
    cudaGetSymbolAddress((void**)&Qf, g_Qfeat);
    cudaGetSymbolAddress((void**)&St, g_state);
    cudaGetSymbolAddress((void**)&Cb, g_comb);
    cudaGetSymbolAddress((void**)&Ac, g_acc);
    cudaGetSymbolAddress((void**)&Q0, g_q0);
    cudaGetSymbolAddress((void**)&Q1, g_q1);
    __half *Xh, *Clh, *Hhh, *Rfh, *Q0h, *Q1h, *Alh;
    __half *ValWh, *R1Wh, *R2Wh, *QuWh, *OutWh;
    cudaGetSymbolAddress((void**)&Xh,  g_xh);
    cudaGetSymbolAddress((void**)&Clh, g_Clh);
    cudaGetSymbolAddress((void**)&Hhh, g_Hhh);
    cudaGetSymbolAddress((void**)&Rfh, g_Rfh);
    cudaGetSymbolAddress((void**)&Q0h, g_q0h);
    cudaGetSymbolAddress((void**)&Q1h, g_q1h);
    cudaGetSymbolAddress((void**)&Alh, g_Alh);
    cudaGetSymbolAddress((void**)&ValWh, g_valwh);
    cudaGetSymbolAddress((void**)&R1Wh, g_r1wh);
    cudaGetSymbolAddress((void**)&R2Wh, g_r2wh);
    cudaGetSymbolAddress((void**)&QuWh, g_quwh);
    cudaGetSymbolAddress((void**)&OutWh, g_outwh);

    // convert weights + x to half (once per launch)
    cvt_h_k<<<512, 256>>>(val_w, r1w, r2w, quw, outw, x);

    // values GEMM (fp16 mma): (4096x256) @ (256x256)^T -> fp32 V
    mma_gemm_k<256, 0, false><<<dim3(cD / 64, cM / 128), 256>>>(
        Xh, nullptr, ValWh, val_b, V, nullptr, nullptr, nullptr, cD, 0);
    // memory-side phase features (fp32)
    phase_gemm_k<<<cM / 32, 256>>>(x, phase_w, phase_b, Mf);
    chunk_partial_k<<<dim3(cNC, cB * cK), 256>>>(Mf, V, St);
    scan_k<<<256, 256>>>(St);

    const float* qin = x;
    const __half* qinh = Xh;
    for (int i = 0; i < cI; i++) {
        float* qout = (i & 1) ? Q1 : Q0;
        __half* qouth = (i & 1) ? Q1h : Q0h;
        phase_gemm_k<<<cM / 32, 256>>>(qin, phase_w, phase_b, Qf);
        retrieve_mma_k<<<dim3(cNC, cB * cK), 256>>>(Qf, Mf, St, V, Cb);
        // LN over 1024 -> half
        ln_h_k<1024><<<cM, 256>>>(Cb, rlnw + (size_t)i * cKD, rlnb + (size_t)i * cKD, Clh);
        // ref1 + gelu -> half h
        mma_gemm_k<1024, 2, false><<<dim3(cH / 64, cM / 128), 256>>>(
            Clh, nullptr, R1Wh + (size_t)i * cH * cKD, r1b + (size_t)i * cH,
            nullptr, Hhh, nullptr, nullptr, cH, 0);
        // ref2 -> half refined + fp32 acc
        mma_gemm_k<512, 3, false><<<dim3(cD / 64, cM / 128), 256>>>(
            Hhh, nullptr, R2Wh + (size_t)i * cD * cH, r2b + (size_t)i * cD,
            nullptr, Rfh, Ac, nullptr, cD, (i == 0) ? 1 : 0);
        // gate: [qin_h | refined_h] -> qout (fp32 + half)
        mma_gemm_k<512, 4, true><<<dim3(cD / 64, cM / 128), 256>>>(
            qinh, Rfh, QuWh + (size_t)i * cD * cH, qub + (size_t)i * cD,
            qout, qouth, nullptr, qin, cD, 0);
        qin = qout;
        qinh = qouth;
    }

    // final: x + LN(acc) @ out_w^T + out_b
    ln_h_k<256><<<cM, 256>>>(Ac, olnw, olnb, Alh);
    mma_gemm_k<256, 5, false><<<dim3(cD / 64, cM / 128), 256>>>(
        Alh, nullptr, OutWh, outb, out, nullptr, nullptr, x, cD, 0);
}